// round 14
// baseline (speedup 1.0000x reference)
#include <cuda_runtime.h>
#include <cuda_fp16.h>
#include <math.h>
#include <stdint.h>

#define NTOK 4096
#define CDIM 1024
#define HDIM 4096
#define NEXP 8

// ---------------------------------------------------------------------------
// Static device scratch (allocation-free per harness rules)
// ---------------------------------------------------------------------------
__device__ int   g_count[NEXP];
__device__ int   g_bucket[NEXP][NTOK];
__device__ float g_wt[NEXP][NTOK];

// fp16 operand planes, K-major everywhere.
__device__ __align__(256) __half g_xg[(size_t)NEXP * NTOK * CDIM];
__device__ __align__(256) __half g_w1t[(size_t)NEXP * HDIM * CDIM];
__device__ __align__(256) __half g_w2t[(size_t)NEXP * CDIM * HDIM];
__device__ __align__(256) __half g_h[(size_t)NEXP * NTOK * HDIM];

// ---------------------------------------------------------------------------
// PTX helpers (generic sm_80+ features only — no tcgen05 on this PTX target)
// ---------------------------------------------------------------------------
__device__ __forceinline__ uint32_t smem_u32(const void* p) {
    uint32_t a;
    asm("{ .reg .u64 t; cvta.to.shared.u64 t, %1; cvt.u32.u64 %0, t; }"
        : "=r"(a) : "l"(p));
    return a;
}
__device__ __forceinline__ void cpa16(uint32_t dst, const void* src) {
    asm volatile("cp.async.cg.shared.global [%0], [%1], 16;"
                 :: "r"(dst), "l"(src) : "memory");
}
__device__ __forceinline__ void cpa_commit() {
    asm volatile("cp.async.commit_group;" ::: "memory");
}
template <int N> __device__ __forceinline__ void cpa_wait() {
    asm volatile("cp.async.wait_group %0;" :: "n"(N) : "memory");
}
__device__ __forceinline__ void ldm_x4(uint32_t* r, uint32_t a) {
    asm volatile("ldmatrix.sync.aligned.m8n8.x4.shared.b16 {%0,%1,%2,%3}, [%4];"
                 : "=r"(r[0]), "=r"(r[1]), "=r"(r[2]), "=r"(r[3]) : "r"(a));
}
__device__ __forceinline__ void mma16816(float* c, const uint32_t* a, const uint32_t* b) {
    asm volatile(
        "mma.sync.aligned.m16n8k16.row.col.f32.f16.f16.f32 "
        "{%0,%1,%2,%3}, {%4,%5,%6,%7}, {%8,%9}, {%0,%1,%2,%3};"
        : "+f"(c[0]), "+f"(c[1]), "+f"(c[2]), "+f"(c[3])
        : "r"(a[0]), "r"(a[1]), "r"(a[2]), "r"(a[3]), "r"(b[0]), "r"(b[1]));
}

// ---------------------------------------------------------------------------
// Zero output + counters
// ---------------------------------------------------------------------------
__global__ void zero_kernel(float* __restrict__ out) {
    size_t i = (size_t)blockIdx.x * blockDim.x + threadIdx.x;
    if (i < (size_t)NTOK * CDIM) out[i] = 0.0f;
    if (i < NEXP) g_count[i] = 0;
}

// ---------------------------------------------------------------------------
// Gating: one warp per token
// ---------------------------------------------------------------------------
__global__ void gate_kernel(const float* __restrict__ x,
                            const float* __restrict__ gw) {
    int gtid = blockIdx.x * blockDim.x + threadIdx.x;
    int tok  = gtid >> 5;
    int lane = threadIdx.x & 31;
    if (tok >= NTOK) return;

    float p[NEXP];
#pragma unroll
    for (int e = 0; e < NEXP; e++) p[e] = 0.0f;
    const float* xr = x + (size_t)tok * CDIM;
    for (int k = lane; k < CDIM; k += 32) {
        float xv = xr[k];
        const float* gr = gw + (size_t)k * NEXP;
#pragma unroll
        for (int e = 0; e < NEXP; e++) p[e] += xv * gr[e];
    }
#pragma unroll
    for (int off = 16; off > 0; off >>= 1)
#pragma unroll
        for (int e = 0; e < NEXP; e++)
            p[e] += __shfl_xor_sync(0xFFFFFFFFu, p[e], off);
    if (lane == 0) {
        int e0 = 0;
#pragma unroll
        for (int e = 1; e < NEXP; e++) if (p[e] > p[e0]) e0 = e;
        int e1 = -1;
#pragma unroll
        for (int e = 0; e < NEXP; e++)
            if (e != e0 && (e1 < 0 || p[e] > p[e1])) e1 = e;
        float w0 = 1.0f / (1.0f + expf(p[e1] - p[e0]));
        float w1 = 1.0f - w0;
        int s0 = atomicAdd(&g_count[e0], 1);
        g_bucket[e0][s0] = tok; g_wt[e0][s0] = w0;
        int s1 = atomicAdd(&g_count[e1], 1);
        g_bucket[e1][s1] = tok; g_wt[e1][s1] = w1;
    }
}

// ---------------------------------------------------------------------------
// Gather + convert x rows into per-expert fp16 planes
// ---------------------------------------------------------------------------
__global__ void convert_x_kernel(const float* __restrict__ x) {
    const int e = blockIdx.y, slot = blockIdx.x;
    if (slot >= g_count[e]) return;
    const int tok = g_bucket[e][slot];
    const float4* src = reinterpret_cast<const float4*>(x + (size_t)tok * CDIM);
    __half2* dst = reinterpret_cast<__half2*>(g_xg + ((size_t)e * NTOK + slot) * CDIM);
    for (int i = threadIdx.x; i < CDIM / 4; i += blockDim.x) {
        float4 v = src[i];
        dst[2 * i]     = __floats2half2_rn(v.x, v.y);
        dst[2 * i + 1] = __floats2half2_rn(v.z, v.w);
    }
}

// ---------------------------------------------------------------------------
// Transpose + convert weights: in [e][KD][ND] fp32 -> out [e][ND][KD] fp16
// ---------------------------------------------------------------------------
template <int KD, int ND, bool W1>
__global__ __launch_bounds__(256) void convert_w_kernel(const float* __restrict__ w) {
    __shared__ float tile[32][33];
    const int e = blockIdx.z;
    const float* we = w + (size_t)e * KD * ND;
    const int n0 = blockIdx.x * 32, k0 = blockIdx.y * 32;
    const int tx = threadIdx.x & 31, ty = threadIdx.x >> 5;  // ty 0..7
#pragma unroll
    for (int i = 0; i < 32; i += 8)
        tile[ty + i][tx] = we[(size_t)(k0 + ty + i) * ND + n0 + tx];
    __syncthreads();
    __half* wt = W1 ? g_w1t : g_w2t;
    const int px = threadIdx.x & 15, py = threadIdx.x >> 4;  // py 0..15
#pragma unroll
    for (int g = 0; g < 2; g++) {
        int r = py + g * 16;  // n-local
        float a = tile[2 * px][r], b = tile[2 * px + 1][r];
        size_t o = ((size_t)e * ND + n0 + r) * KD + k0 + 2 * px;
        *reinterpret_cast<__half2*>(wt + o) = __floats2half2_rn(a, b);
    }
}

// ---------------------------------------------------------------------------
// Pipelined fp16 mma.sync GEMM with optional split-K.
// CTA tile 128x256, BK=32, 4 stages (24KB/stage, 96KB). 8 warps, each 64x64.
// blockIdx.x encodes (jt, sk): jt = x % (NDIM/256), sk = x / (NDIM/256).
// Each split handles K range [sk*KTOT/KSPLIT, ...). Split 0 adds bias.
// fp32 accumulate. 64B smem rows, 4 chunks of 16B:
//   phys_chunk = c ^ ((row>>1)&3)   (conflict-free stores + ldmatrix)
// ---------------------------------------------------------------------------
#define GSTAGES 4
#define STAGE_B 24576
#define GSMEM   (GSTAGES * STAGE_B)

template <int KTOT, int NDIM, bool G1, int KSPLIT>
__global__ __launch_bounds__(256, 1) void moe_gemm_kernel(
    const float* __restrict__ bias, float* __restrict__ outp) {
    constexpr int JT = NDIM / 256;
    const int e = blockIdx.z, mt = blockIdx.y;
    const int jt = blockIdx.x % JT, sk = blockIdx.x / JT;
    const int T = g_count[e];
    if (mt * 128 >= T) return;

    extern __shared__ __align__(1024) char smem[];
    const uint32_t sm = smem_u32(smem);
    const int tid = threadIdx.x, wid = tid >> 5, lane = tid & 31;
    const int warp_m = wid >> 2, warp_n = wid & 3;  // 2 x 4 warps (64m x 64n)

    constexpr int NC = KTOT / 32 / KSPLIT;   // chunks per split
    const int kcb = sk * NC;                 // chunk base for this split

    const __half* aBase =
        (G1 ? g_xg : g_h) + ((size_t)e * NTOK + mt * 128) * KTOT;
    const __half* bBase =
        (G1 ? g_w1t : g_w2t) + ((size_t)e * NDIM + jt * 256) * KTOT;

    float acc[4][8][4];
#pragma unroll
    for (int mi = 0; mi < 4; mi++)
#pragma unroll
        for (int ni = 0; ni < 8; ni++)
#pragma unroll
            for (int r = 0; r < 4; r++) acc[mi][ni][r] = 0.0f;

    // stage: A 128x32 (8KB) at +0, B 256x32 (16KB) at +8192
    auto load_chunk = [&](int kc, int stg) {
        const int kk = (kcb + kc) * 32;
        const __half* asrc = aBase + kk;
        const __half* bsrc = bBase + kk;
        const uint32_t abase = sm + stg * STAGE_B;
        const uint32_t bbase = abase + 8192;
#pragma unroll
        for (int i = 0; i < 2; i++) {   // A: 512 x 16B units
            int u = tid + i * 256;
            int row = u >> 2, c = u & 3;
            int pc = c ^ ((row >> 1) & 3);
            cpa16(abase + row * 64 + pc * 16, asrc + (size_t)row * KTOT + c * 8);
        }
#pragma unroll
        for (int i = 0; i < 4; i++) {   // B: 1024 x 16B units
            int u = tid + i * 256;
            int row = u >> 2, c = u & 3;
            int pc = c ^ ((row >> 1) & 3);
            cpa16(bbase + row * 64 + pc * 16, bsrc + (size_t)row * KTOT + c * 8);
        }
    };

    // register fragments for k-half kh (0..1) of stage stg
    auto frag_load = [&](int stg, int kh, uint32_t a[4][4], uint32_t b[8][2]) {
        const uint32_t sA = sm + stg * STAGE_B;
        const uint32_t sB = sA + 8192;
#pragma unroll
        for (int mi = 0; mi < 4; mi++) {
            int row = warp_m * 64 + mi * 16 + (lane & 15);
            int c = kh * 2 + (lane >> 4);
            int pc = c ^ ((row >> 1) & 3);
            ldm_x4(a[mi], sA + row * 64 + pc * 16);
        }
#pragma unroll
        for (int p = 0; p < 4; p++) {   // each x4: 2 n-groups x 2 k-halves
            int row = warp_n * 64 + p * 16 + ((lane >> 4) & 1) * 8 + (lane & 7);
            int c = kh * 2 + ((lane >> 3) & 1);
            int pc = c ^ ((row >> 1) & 3);
            uint32_t t[4];
            ldm_x4(t, sB + row * 64 + pc * 16);
            b[p * 2][0] = t[0]; b[p * 2][1] = t[1];
            b[p * 2 + 1][0] = t[2]; b[p * 2 + 1][1] = t[3];
        }
    };

    uint32_t af[2][4][4], bf[2][8][2];

    // prologue: prefetch chunks 0..2
#pragma unroll
    for (int s = 0; s < GSTAGES - 1; s++) {
        if (s < NC) load_chunk(s, s);
        cpa_commit();
    }

    for (int kc = 0; kc < NC; kc++) {
        cpa_wait<GSTAGES - 2>();
        __syncthreads();
        const int nx = kc + GSTAGES - 1;
        if (nx < NC) load_chunk(nx, nx & (GSTAGES - 1));
        cpa_commit();
        const int stg = kc & (GSTAGES - 1);
        frag_load(stg, 0, af[0], bf[0]);
#pragma unroll
        for (int kh = 0; kh < 2; kh++) {
            if (kh == 0) frag_load(stg, 1, af[1], bf[1]);
            uint32_t (*a)[4] = af[kh];
            uint32_t (*b)[2] = bf[kh];
#pragma unroll
            for (int mi = 0; mi < 4; mi++)
#pragma unroll
                for (int ni = 0; ni < 8; ni++)
                    mma16816(acc[mi][ni], a[mi], b[ni]);
        }
    }

    // ----- epilogue -----
    const bool add_bias = (sk == 0);
#pragma unroll
    for (int mi = 0; mi < 4; mi++) {
        const int m0 = mt * 128 + warp_m * 64 + mi * 16 + (lane >> 2);
#pragma unroll
        for (int half = 0; half < 2; half++) {
            const int m = m0 + half * 8;
            if (m >= T) continue;
            if (G1) {
                const size_t hrow = ((size_t)e * NTOK + m) * HDIM;
#pragma unroll
                for (int ni = 0; ni < 8; ni++) {
                    int n = jt * 256 + warp_n * 64 + ni * 8 + (lane & 3) * 2;
                    float v0 = acc[mi][ni][half * 2 + 0] + bias[e * NDIM + n];
                    float v1 = acc[mi][ni][half * 2 + 1] + bias[e * NDIM + n + 1];
                    float g0 = 0.5f * v0 * (1.0f + erff(v0 * 0.70710678118654752f));
                    float g1 = 0.5f * v1 * (1.0f + erff(v1 * 0.70710678118654752f));
                    *reinterpret_cast<__half2*>(g_h + hrow + n) =
                        __floats2half2_rn(g0, g1);
                }
            } else {
                const int tokn = g_bucket[e][m];
                const float wc = g_wt[e][m];
                float* orow = outp + (size_t)tokn * CDIM;
#pragma unroll
                for (int ni = 0; ni < 8; ni++) {
                    int n = jt * 256 + warp_n * 64 + ni * 8 + (lane & 3) * 2;
                    float b0 = add_bias ? bias[e * NDIM + n]     : 0.0f;
                    float b1 = add_bias ? bias[e * NDIM + n + 1] : 0.0f;
                    float v0 = acc[mi][ni][half * 2 + 0] + b0;
                    float v1 = acc[mi][ni][half * 2 + 1] + b1;
                    atomicAdd(orow + n, wc * v0);
                    atomicAdd(orow + n + 1, wc * v1);
                }
            }
        }
    }
}

// ---------------------------------------------------------------------------
// Launch
// ---------------------------------------------------------------------------
extern "C" void kernel_launch(void* const* d_in, const int* in_sizes, int n_in,
                              void* d_out, int out_size) {
    const float* x  = (const float*)d_in[0];
    const float* gw = (const float*)d_in[1];
    const float* w1 = (const float*)d_in[2];
    const float* b1 = (const float*)d_in[3];
    const float* w2 = (const float*)d_in[4];
    const float* b2 = (const float*)d_in[5];
    float* out = (float*)d_out;

    cudaFuncSetAttribute((const void*)moe_gemm_kernel<CDIM, HDIM, true, 1>,
                         cudaFuncAttributeMaxDynamicSharedMemorySize, GSMEM);
    cudaFuncSetAttribute((const void*)moe_gemm_kernel<HDIM, CDIM, false, 4>,
                         cudaFuncAttributeMaxDynamicSharedMemorySize, GSMEM);

    zero_kernel<<<(NTOK * CDIM + 255) / 256, 256>>>(out);
    gate_kernel<<<NTOK / 4, 128>>>(x, gw);
    convert_x_kernel<<<dim3(NTOK, NEXP), 128>>>(x);
    convert_w_kernel<CDIM, HDIM, true><<<dim3(HDIM / 32, CDIM / 32, NEXP), 256>>>(w1);
    convert_w_kernel<HDIM, CDIM, false><<<dim3(CDIM / 32, HDIM / 32, NEXP), 256>>>(w2);

    // GEMM1: no split-K (gelu epilogue), 16 jt tiles
    moe_gemm_kernel<CDIM, HDIM, true, 1>
        <<<dim3(HDIM / 256, NTOK / 128, NEXP), 256, GSMEM>>>(b1, nullptr);
    // GEMM2: split-K = 4 -> blockIdx.x = jt (4) x sk (4) = 16
    moe_gemm_kernel<HDIM, CDIM, false, 4>
        <<<dim3((CDIM / 256) * 4, NTOK / 128, NEXP), 256, GSMEM>>>(b2, out);
}

// round 15
// speedup vs baseline: 1.0297x; 1.0297x over previous
#include <cuda_runtime.h>
#include <cuda_fp16.h>
#include <math.h>
#include <stdint.h>

#define NTOK 4096
#define CDIM 1024
#define HDIM 4096
#define NEXP 8

// ---------------------------------------------------------------------------
// Static device scratch (allocation-free per harness rules)
// ---------------------------------------------------------------------------
__device__ int   g_count[NEXP];
__device__ int   g_bucket[NEXP][NTOK];
__device__ float g_wt[NEXP][NTOK];

// fp16 operand planes, K-major everywhere.
__device__ __align__(256) __half g_x16[(size_t)NTOK * CDIM];
__device__ __align__(256) __half g_w1t[(size_t)NEXP * HDIM * CDIM];
__device__ __align__(256) __half g_w2t[(size_t)NEXP * CDIM * HDIM];
__device__ __align__(256) __half g_h[(size_t)NEXP * NTOK * HDIM];

// ---------------------------------------------------------------------------
// PTX helpers (generic sm_80+ features only — no tcgen05 on this PTX target)
// ---------------------------------------------------------------------------
__device__ __forceinline__ uint32_t smem_u32(const void* p) {
    uint32_t a;
    asm("{ .reg .u64 t; cvta.to.shared.u64 t, %1; cvt.u32.u64 %0, t; }"
        : "=r"(a) : "l"(p));
    return a;
}
__device__ __forceinline__ void cpa16(uint32_t dst, const void* src) {
    asm volatile("cp.async.cg.shared.global [%0], [%1], 16;"
                 :: "r"(dst), "l"(src) : "memory");
}
__device__ __forceinline__ void cpa_commit() {
    asm volatile("cp.async.commit_group;" ::: "memory");
}
template <int N> __device__ __forceinline__ void cpa_wait() {
    asm volatile("cp.async.wait_group %0;" :: "n"(N) : "memory");
}
__device__ __forceinline__ void ldm_x4(uint32_t* r, uint32_t a) {
    asm volatile("ldmatrix.sync.aligned.m8n8.x4.shared.b16 {%0,%1,%2,%3}, [%4];"
                 : "=r"(r[0]), "=r"(r[1]), "=r"(r[2]), "=r"(r[3]) : "r"(a));
}
__device__ __forceinline__ void mma16816(float* c, const uint32_t* a, const uint32_t* b) {
    asm volatile(
        "mma.sync.aligned.m16n8k16.row.col.f32.f16.f16.f32 "
        "{%0,%1,%2,%3}, {%4,%5,%6,%7}, {%8,%9}, {%0,%1,%2,%3};"
        : "+f"(c[0]), "+f"(c[1]), "+f"(c[2]), "+f"(c[3])
        : "r"(a[0]), "r"(a[1]), "r"(a[2]), "r"(a[3]), "r"(b[0]), "r"(b[1]));
}

// ---------------------------------------------------------------------------
// Zero output + counters
// ---------------------------------------------------------------------------
__global__ void zero_kernel(float* __restrict__ out) {
    size_t i = (size_t)blockIdx.x * blockDim.x + threadIdx.x;
    if (i < (size_t)NTOK * CDIM) out[i] = 0.0f;
    if (i < NEXP) g_count[i] = 0;
}

// ---------------------------------------------------------------------------
// Gating: one warp per token
// ---------------------------------------------------------------------------
__global__ void gate_kernel(const float* __restrict__ x,
                            const float* __restrict__ gw) {
    int gtid = blockIdx.x * blockDim.x + threadIdx.x;
    int tok  = gtid >> 5;
    int lane = threadIdx.x & 31;
    if (tok >= NTOK) return;

    float p[NEXP];
#pragma unroll
    for (int e = 0; e < NEXP; e++) p[e] = 0.0f;
    const float* xr = x + (size_t)tok * CDIM;
    for (int k = lane; k < CDIM; k += 32) {
        float xv = xr[k];
        const float* gr = gw + (size_t)k * NEXP;
#pragma unroll
        for (int e = 0; e < NEXP; e++) p[e] += xv * gr[e];
    }
#pragma unroll
    for (int off = 16; off > 0; off >>= 1)
#pragma unroll
        for (int e = 0; e < NEXP; e++)
            p[e] += __shfl_xor_sync(0xFFFFFFFFu, p[e], off);
    if (lane == 0) {
        int e0 = 0;
#pragma unroll
        for (int e = 1; e < NEXP; e++) if (p[e] > p[e0]) e0 = e;
        int e1 = -1;
#pragma unroll
        for (int e = 0; e < NEXP; e++)
            if (e != e0 && (e1 < 0 || p[e] > p[e1])) e1 = e;
        float w0 = 1.0f / (1.0f + expf(p[e1] - p[e0]));
        float w1 = 1.0f - w0;
        int s0 = atomicAdd(&g_count[e0], 1);
        g_bucket[e0][s0] = tok; g_wt[e0][s0] = w0;
        int s1 = atomicAdd(&g_count[e1], 1);
        g_bucket[e1][s1] = tok; g_wt[e1][s1] = w1;
    }
}

// ---------------------------------------------------------------------------
// Plain streaming convert: x fp32 -> fp16 (no gather; GEMM1 gathers rows)
// ---------------------------------------------------------------------------
__global__ void convert_x_kernel(const float* __restrict__ x) {
    size_t i = (size_t)blockIdx.x * blockDim.x + threadIdx.x;
    if (i >= (size_t)NTOK * CDIM / 4) return;
    float4 v = reinterpret_cast<const float4*>(x)[i];
    __half2* dst = reinterpret_cast<__half2*>(g_x16);
    dst[2 * i]     = __floats2half2_rn(v.x, v.y);
    dst[2 * i + 1] = __floats2half2_rn(v.z, v.w);
}

// ---------------------------------------------------------------------------
// Transpose + convert weights: in [e][KD][ND] fp32 -> out [e][ND][KD] fp16
// ---------------------------------------------------------------------------
template <int KD, int ND, bool W1>
__global__ __launch_bounds__(256) void convert_w_kernel(const float* __restrict__ w) {
    __shared__ float tile[32][33];
    const int e = blockIdx.z;
    const float* we = w + (size_t)e * KD * ND;
    const int n0 = blockIdx.x * 32, k0 = blockIdx.y * 32;
    const int tx = threadIdx.x & 31, ty = threadIdx.x >> 5;  // ty 0..7
#pragma unroll
    for (int i = 0; i < 32; i += 8)
        tile[ty + i][tx] = we[(size_t)(k0 + ty + i) * ND + n0 + tx];
    __syncthreads();
    __half* wt = W1 ? g_w1t : g_w2t;
    const int px = threadIdx.x & 15, py = threadIdx.x >> 4;  // py 0..15
#pragma unroll
    for (int g = 0; g < 2; g++) {
        int r = py + g * 16;  // n-local
        float a = tile[2 * px][r], b = tile[2 * px + 1][r];
        size_t o = ((size_t)e * ND + n0 + r) * KD + k0 + 2 * px;
        *reinterpret_cast<__half2*>(wt + o) = __floats2half2_rn(a, b);
    }
}

// ---------------------------------------------------------------------------
// Pipelined fp16 mma.sync GEMM.
// CTA tile 128x256, BK=32, 4 stages (24KB/stage, 96KB). 8 warps, each 64x64.
// G1: A rows gathered from g_x16 via g_bucket (two fixed rows per thread,
// resolved to base pointers before the mainloop). G2: A dense from g_h.
// fp32 accumulate. 64B smem rows, 4 chunks of 16B:
//   phys_chunk = c ^ ((row>>1)&3)   (conflict-free stores + ldmatrix)
// ---------------------------------------------------------------------------
#define GSTAGES 4
#define STAGE_B 24576
#define GSMEM   (GSTAGES * STAGE_B)

template <int KTOT, int NDIM, bool G1>
__global__ __launch_bounds__(256, 1) void moe_gemm_kernel(
    const float* __restrict__ bias, float* __restrict__ outp) {
    const int e = blockIdx.z, mt = blockIdx.y, jt = blockIdx.x;
    const int T = g_count[e];
    if (mt * 128 >= T) return;

    extern __shared__ __align__(1024) char smem[];
    const uint32_t sm = smem_u32(smem);
    const int tid = threadIdx.x, wid = tid >> 5, lane = tid & 31;
    const int warp_m = wid >> 2, warp_n = wid & 3;  // 2 x 4 warps (64m x 64n)

    constexpr int NC = KTOT / 32;

    const __half* bBase =
        (G1 ? g_w1t : g_w2t) + ((size_t)e * NDIM + jt * 256) * KTOT;

    // A-row base pointers for this thread's two cp.async rows
    const int ra0 = tid >> 2;          // 0..63
    const int ra1 = ra0 + 64;          // 64..127
    const int ac  = tid & 3;           // 16B chunk within 64B row
    const __half *pA0, *pA1;
    if (G1) {
        int m0g = mt * 128 + ra0, m1g = mt * 128 + ra1;
        int t0 = (m0g < T) ? g_bucket[e][m0g] : 0;
        int t1 = (m1g < T) ? g_bucket[e][m1g] : 0;
        pA0 = g_x16 + (size_t)t0 * KTOT;
        pA1 = g_x16 + (size_t)t1 * KTOT;
    } else {
        const __half* aBase = g_h + ((size_t)e * NTOK + mt * 128) * KTOT;
        pA0 = aBase + (size_t)ra0 * KTOT;
        pA1 = aBase + (size_t)ra1 * KTOT;
    }
    const int apc0 = ac ^ ((ra0 >> 1) & 3);
    const int apc1 = ac ^ ((ra1 >> 1) & 3);

    float acc[4][8][4];
#pragma unroll
    for (int mi = 0; mi < 4; mi++)
#pragma unroll
        for (int ni = 0; ni < 8; ni++)
#pragma unroll
            for (int r = 0; r < 4; r++) acc[mi][ni][r] = 0.0f;

    // stage: A 128x32 (8KB) at +0, B 256x32 (16KB) at +8192
    auto load_chunk = [&](int kc, int stg) {
        const int kk = kc * 32;
        const uint32_t abase = sm + stg * STAGE_B;
        const uint32_t bbase = abase + 8192;
        cpa16(abase + ra0 * 64 + apc0 * 16, pA0 + kk + ac * 8);
        cpa16(abase + ra1 * 64 + apc1 * 16, pA1 + kk + ac * 8);
        const __half* bsrc = bBase + kk;
#pragma unroll
        for (int i = 0; i < 4; i++) {   // B: 1024 x 16B units
            int u = tid + i * 256;
            int row = u >> 2, c = u & 3;
            int pc = c ^ ((row >> 1) & 3);
            cpa16(bbase + row * 64 + pc * 16, bsrc + (size_t)row * KTOT + c * 8);
        }
    };

    // register fragments for k-half kh (0..1) of stage stg
    auto frag_load = [&](int stg, int kh, uint32_t a[4][4], uint32_t b[8][2]) {
        const uint32_t sA = sm + stg * STAGE_B;
        const uint32_t sB = sA + 8192;
#pragma unroll
        for (int mi = 0; mi < 4; mi++) {
            int row = warp_m * 64 + mi * 16 + (lane & 15);
            int c = kh * 2 + (lane >> 4);
            int pc = c ^ ((row >> 1) & 3);
            ldm_x4(a[mi], sA + row * 64 + pc * 16);
        }
#pragma unroll
        for (int p = 0; p < 4; p++) {   // each x4: 2 n-groups x 2 k-halves
            int row = warp_n * 64 + p * 16 + ((lane >> 4) & 1) * 8 + (lane & 7);
            int c = kh * 2 + ((lane >> 3) & 1);
            int pc = c ^ ((row >> 1) & 3);
            uint32_t t[4];
            ldm_x4(t, sB + row * 64 + pc * 16);
            b[p * 2][0] = t[0]; b[p * 2][1] = t[1];
            b[p * 2 + 1][0] = t[2]; b[p * 2 + 1][1] = t[3];
        }
    };

    uint32_t af[2][4][4], bf[2][8][2];

    // prologue: prefetch chunks 0..2
#pragma unroll
    for (int s = 0; s < GSTAGES - 1; s++) {
        if (s < NC) load_chunk(s, s);
        cpa_commit();
    }

    for (int kc = 0; kc < NC; kc++) {
        cpa_wait<GSTAGES - 2>();
        __syncthreads();
        const int nx = kc + GSTAGES - 1;
        if (nx < NC) load_chunk(nx, nx & (GSTAGES - 1));
        cpa_commit();
        const int stg = kc & (GSTAGES - 1);
        frag_load(stg, 0, af[0], bf[0]);
#pragma unroll
        for (int kh = 0; kh < 2; kh++) {
            if (kh == 0) frag_load(stg, 1, af[1], bf[1]);
            uint32_t (*a)[4] = af[kh];
            uint32_t (*b)[2] = bf[kh];
#pragma unroll
            for (int mi = 0; mi < 4; mi++)
#pragma unroll
                for (int ni = 0; ni < 8; ni++)
                    mma16816(acc[mi][ni], a[mi], b[ni]);
        }
    }

    // ----- epilogue -----
#pragma unroll
    for (int mi = 0; mi < 4; mi++) {
        const int m0 = mt * 128 + warp_m * 64 + mi * 16 + (lane >> 2);
#pragma unroll
        for (int half = 0; half < 2; half++) {
            const int m = m0 + half * 8;
            if (m >= T) continue;
            if (G1) {
                const size_t hrow = ((size_t)e * NTOK + m) * HDIM;
#pragma unroll
                for (int ni = 0; ni < 8; ni++) {
                    int n = jt * 256 + warp_n * 64 + ni * 8 + (lane & 3) * 2;
                    float v0 = acc[mi][ni][half * 2 + 0] + bias[e * NDIM + n];
                    float v1 = acc[mi][ni][half * 2 + 1] + bias[e * NDIM + n + 1];
                    float g0 = 0.5f * v0 * (1.0f + erff(v0 * 0.70710678118654752f));
                    float g1 = 0.5f * v1 * (1.0f + erff(v1 * 0.70710678118654752f));
                    *reinterpret_cast<__half2*>(g_h + hrow + n) =
                        __floats2half2_rn(g0, g1);
                }
            } else {
                const int tokn = g_bucket[e][m];
                const float wc = g_wt[e][m];
                float* orow = outp + (size_t)tokn * CDIM;
#pragma unroll
                for (int ni = 0; ni < 8; ni++) {
                    int n = jt * 256 + warp_n * 64 + ni * 8 + (lane & 3) * 2;
                    float v0 = acc[mi][ni][half * 2 + 0] + bias[e * NDIM + n];
                    float v1 = acc[mi][ni][half * 2 + 1] + bias[e * NDIM + n + 1];
                    atomicAdd(orow + n, wc * v0);
                    atomicAdd(orow + n + 1, wc * v1);
                }
            }
        }
    }
}

// ---------------------------------------------------------------------------
// Launch: fork convert_w1/convert_w2 onto side streams; convert_w2 overlaps
// GEMM1. Event fork/join is graph-capturable. Streams/events are host-side
// objects created once (no device memory).
// ---------------------------------------------------------------------------
extern "C" void kernel_launch(void* const* d_in, const int* in_sizes, int n_in,
                              void* d_out, int out_size) {
    const float* x  = (const float*)d_in[0];
    const float* gw = (const float*)d_in[1];
    const float* w1 = (const float*)d_in[2];
    const float* b1 = (const float*)d_in[3];
    const float* w2 = (const float*)d_in[4];
    const float* b2 = (const float*)d_in[5];
    float* out = (float*)d_out;

    static cudaStream_t s1 = nullptr, s2 = nullptr;
    static cudaEvent_t e_fork = nullptr, e_w1 = nullptr, e_w2 = nullptr;
    if (s1 == nullptr) {
        cudaStreamCreateWithFlags(&s1, cudaStreamNonBlocking);
        cudaStreamCreateWithFlags(&s2, cudaStreamNonBlocking);
        cudaEventCreateWithFlags(&e_fork, cudaEventDisableTiming);
        cudaEventCreateWithFlags(&e_w1, cudaEventDisableTiming);
        cudaEventCreateWithFlags(&e_w2, cudaEventDisableTiming);
        cudaFuncSetAttribute((const void*)moe_gemm_kernel<CDIM, HDIM, true>,
                             cudaFuncAttributeMaxDynamicSharedMemorySize, GSMEM);
        cudaFuncSetAttribute((const void*)moe_gemm_kernel<HDIM, CDIM, false>,
                             cudaFuncAttributeMaxDynamicSharedMemorySize, GSMEM);
    }

    // fork point on the (possibly capturing) default stream
    cudaEventRecord(e_fork, 0);
    cudaStreamWaitEvent(s1, e_fork, 0);
    cudaStreamWaitEvent(s2, e_fork, 0);

    // side stream 1: w1 transpose+convert (needed before GEMM1)
    convert_w_kernel<CDIM, HDIM, true>
        <<<dim3(HDIM / 32, CDIM / 32, NEXP), 256, 0, s1>>>(w1);
    cudaEventRecord(e_w1, s1);

    // side stream 2: w2 transpose+convert (needed only before GEMM2 —
    // overlaps gate/convert_x/GEMM1)
    convert_w_kernel<HDIM, CDIM, false>
        <<<dim3(CDIM / 32, HDIM / 32, NEXP), 256, 0, s2>>>(w2);
    cudaEventRecord(e_w2, s2);

    // main stream: routing + x convert
    zero_kernel<<<(NTOK * CDIM + 255) / 256, 256>>>(out);
    gate_kernel<<<NTOK / 4, 128>>>(x, gw);
    convert_x_kernel<<<NTOK * CDIM / 4 / 256, 256>>>(x);

    // GEMM1 (needs w1t + routing + x16)
    cudaStreamWaitEvent(0, e_w1, 0);
    moe_gemm_kernel<CDIM, HDIM, true>
        <<<dim3(HDIM / 256, NTOK / 128, NEXP), 256, GSMEM>>>(b1, nullptr);

    // GEMM2 (needs w2t + g_h)
    cudaStreamWaitEvent(0, e_w2, 0);
    moe_gemm_kernel<HDIM, CDIM, false>
        <<<dim3(CDIM / 256, NTOK / 128, NEXP), 256, GSMEM>>>(b2, out);
}

// round 17
// speedup vs baseline: 1.0660x; 1.0353x over previous
#include <cuda_runtime.h>
#include <cuda_fp16.h>
#include <math.h>
#include <stdint.h>

#define NTOK 4096
#define CDIM 1024
#define HDIM 4096
#define NEXP 8

// ---------------------------------------------------------------------------
// Static device scratch (allocation-free per harness rules)
// ---------------------------------------------------------------------------
__device__ int     g_count[NEXP];
__device__ int     g_bucket[NEXP][NTOK];
__device__ float   g_wt[NEXP][NTOK];
__device__ int8_t  g_slot[NEXP][NTOK];

// fp16 operand planes, K-major everywhere.
__device__ __align__(256) __half g_x16[(size_t)NTOK * CDIM];
__device__ __align__(256) __half g_w1t[(size_t)NEXP * HDIM * CDIM];
__device__ __align__(256) __half g_w2t[(size_t)NEXP * CDIM * HDIM];
__device__ __align__(256) __half g_h[(size_t)NEXP * NTOK * HDIM];
// slot-partitioned GEMM2 output (no atomics; every (slot,token) written once)
__device__ __align__(256) float g_part[2][(size_t)NTOK * CDIM];

// ---------------------------------------------------------------------------
// PTX helpers (generic sm_80+ features only — no tcgen05 on this PTX target)
// ---------------------------------------------------------------------------
__device__ __forceinline__ uint32_t smem_u32(const void* p) {
    uint32_t a;
    asm("{ .reg .u64 t; cvta.to.shared.u64 t, %1; cvt.u32.u64 %0, t; }"
        : "=r"(a) : "l"(p));
    return a;
}
__device__ __forceinline__ void cpa16(uint32_t dst, const void* src) {
    asm volatile("cp.async.cg.shared.global [%0], [%1], 16;"
                 :: "r"(dst), "l"(src) : "memory");
}
__device__ __forceinline__ void cpa_commit() {
    asm volatile("cp.async.commit_group;" ::: "memory");
}
template <int N> __device__ __forceinline__ void cpa_wait() {
    asm volatile("cp.async.wait_group %0;" :: "n"(N) : "memory");
}
__device__ __forceinline__ void ldm_x4(uint32_t* r, uint32_t a) {
    asm volatile("ldmatrix.sync.aligned.m8n8.x4.shared.b16 {%0,%1,%2,%3}, [%4];"
                 : "=r"(r[0]), "=r"(r[1]), "=r"(r[2]), "=r"(r[3]) : "r"(a));
}
__device__ __forceinline__ void mma16816(float* c, const uint32_t* a, const uint32_t* b) {
    asm volatile(
        "mma.sync.aligned.m16n8k16.row.col.f32.f16.f16.f32 "
        "{%0,%1,%2,%3}, {%4,%5,%6,%7}, {%8,%9}, {%0,%1,%2,%3};"
        : "+f"(c[0]), "+f"(c[1]), "+f"(c[2]), "+f"(c[3])
        : "r"(a[0]), "r"(a[1]), "r"(a[2]), "r"(a[3]), "r"(b[0]), "r"(b[1]));
}

// ---------------------------------------------------------------------------
// Init: zero expert counters only (out needs no zeroing — combine overwrites)
// ---------------------------------------------------------------------------
__global__ void init_kernel() {
    if (threadIdx.x < NEXP) g_count[threadIdx.x] = 0;
}

// ---------------------------------------------------------------------------
// Gating: one warp per token, MLP-8 float4 x loads, vectorized gw loads.
// ---------------------------------------------------------------------------
__global__ __launch_bounds__(256) void gate_kernel(const float* __restrict__ x,
                                                   const float* __restrict__ gw) {
    const int tok  = blockIdx.x * 8 + (threadIdx.x >> 5);
    const int lane = threadIdx.x & 31;

    const float4* xr4 = reinterpret_cast<const float4*>(x + (size_t)tok * CDIM);
    float p[NEXP];
#pragma unroll
    for (int e = 0; e < NEXP; e++) p[e] = 0.0f;

#pragma unroll
    for (int i = 0; i < 8; i++) {
        const float4 v = xr4[lane + 32 * i];
        const int k = (lane + 32 * i) * 4;
        const float4* g4 = reinterpret_cast<const float4*>(gw + (size_t)k * NEXP);
#pragma unroll
        for (int j = 0; j < 4; j++) {
            const float xv = (j == 0) ? v.x : (j == 1) ? v.y : (j == 2) ? v.z : v.w;
            const float4 ga = g4[j * 2], gb = g4[j * 2 + 1];
            p[0] += xv * ga.x; p[1] += xv * ga.y;
            p[2] += xv * ga.z; p[3] += xv * ga.w;
            p[4] += xv * gb.x; p[5] += xv * gb.y;
            p[6] += xv * gb.z; p[7] += xv * gb.w;
        }
    }
#pragma unroll
    for (int off = 16; off > 0; off >>= 1)
#pragma unroll
        for (int e = 0; e < NEXP; e++)
            p[e] += __shfl_xor_sync(0xFFFFFFFFu, p[e], off);
    if (lane == 0) {
        int e0 = 0;
#pragma unroll
        for (int e = 1; e < NEXP; e++) if (p[e] > p[e0]) e0 = e;
        int e1 = -1;
#pragma unroll
        for (int e = 0; e < NEXP; e++)
            if (e != e0 && (e1 < 0 || p[e] > p[e1])) e1 = e;
        float w0 = 1.0f / (1.0f + expf(p[e1] - p[e0]));
        float w1 = 1.0f - w0;
        int s0 = atomicAdd(&g_count[e0], 1);
        g_bucket[e0][s0] = tok; g_wt[e0][s0] = w0; g_slot[e0][s0] = 0;
        int s1 = atomicAdd(&g_count[e1], 1);
        g_bucket[e1][s1] = tok; g_wt[e1][s1] = w1; g_slot[e1][s1] = 1;
    }
}

// ---------------------------------------------------------------------------
// Plain streaming convert: x fp32 -> fp16 (no gather; GEMM1 gathers rows)
// ---------------------------------------------------------------------------
__global__ void convert_x_kernel(const float* __restrict__ x) {
    size_t i = (size_t)blockIdx.x * blockDim.x + threadIdx.x;
    if (i >= (size_t)NTOK * CDIM / 4) return;
    float4 v = reinterpret_cast<const float4*>(x)[i];
    __half2* dst = reinterpret_cast<__half2*>(g_x16);
    dst[2 * i]     = __floats2half2_rn(v.x, v.y);
    dst[2 * i + 1] = __floats2half2_rn(v.z, v.w);
}

// ---------------------------------------------------------------------------
// Transpose + convert weights: in [e][KD][ND] fp32 -> out [e][ND][KD] fp16
// ---------------------------------------------------------------------------
template <int KD, int ND, bool W1>
__global__ __launch_bounds__(256) void convert_w_kernel(const float* __restrict__ w) {
    __shared__ float tile[32][33];
    const int e = blockIdx.z;
    const float* we = w + (size_t)e * KD * ND;
    const int n0 = blockIdx.x * 32, k0 = blockIdx.y * 32;
    const int tx = threadIdx.x & 31, ty = threadIdx.x >> 5;  // ty 0..7
#pragma unroll
    for (int i = 0; i < 32; i += 8)
        tile[ty + i][tx] = we[(size_t)(k0 + ty + i) * ND + n0 + tx];
    __syncthreads();
    __half* wt = W1 ? g_w1t : g_w2t;
    const int px = threadIdx.x & 15, py = threadIdx.x >> 4;  // py 0..15
#pragma unroll
    for (int g = 0; g < 2; g++) {
        int r = py + g * 16;  // n-local
        float a = tile[2 * px][r], b = tile[2 * px + 1][r];
        size_t o = ((size_t)e * ND + n0 + r) * KD + k0 + 2 * px;
        *reinterpret_cast<__half2*>(wt + o) = __floats2half2_rn(a, b);
    }
}

// ---------------------------------------------------------------------------
// Combine: out = part0 + part1
// ---------------------------------------------------------------------------
__global__ void combine_kernel(float* __restrict__ out) {
    size_t i = (size_t)blockIdx.x * blockDim.x + threadIdx.x;
    if (i >= (size_t)NTOK * CDIM / 4) return;
    float4 a = reinterpret_cast<const float4*>(g_part[0])[i];
    float4 b = reinterpret_cast<const float4*>(g_part[1])[i];
    float4 r;
    r.x = a.x + b.x; r.y = a.y + b.y; r.z = a.z + b.z; r.w = a.w + b.w;
    reinterpret_cast<float4*>(out)[i] = r;
}

// ---------------------------------------------------------------------------
// Pipelined fp16 mma.sync GEMM.
// CTA tile 128x256, BK=32, 4 stages (24KB/stage, 96KB). 8 warps, each 64x64.
// G1: A rows gathered from g_x16 via g_bucket; epilogue gelu -> g_h (fp16).
// G2: A dense from g_h; epilogue wc*(acc+bias) -> g_part[slot][tok] via STG.
// fp32 accumulate. 64B smem rows, 4 chunks of 16B:
//   phys_chunk = c ^ ((row>>1)&3)   (conflict-free stores + ldmatrix)
// ---------------------------------------------------------------------------
#define GSTAGES 4
#define STAGE_B 24576
#define GSMEM   (GSTAGES * STAGE_B)

template <int KTOT, int NDIM, bool G1>
__global__ __launch_bounds__(256, 1) void moe_gemm_kernel(
    const float* __restrict__ bias) {
    const int e = blockIdx.z, mt = blockIdx.y, jt = blockIdx.x;
    const int T = g_count[e];
    if (mt * 128 >= T) return;

    extern __shared__ __align__(1024) char smem[];
    const uint32_t sm = smem_u32(smem);
    const int tid = threadIdx.x, wid = tid >> 5, lane = tid & 31;
    const int warp_m = wid >> 2, warp_n = wid & 3;  // 2 x 4 warps (64m x 64n)

    constexpr int NC = KTOT / 32;

    const __half* bBase =
        (G1 ? g_w1t : g_w2t) + ((size_t)e * NDIM + jt * 256) * KTOT;

    // A-row base pointers for this thread's two cp.async rows
    const int ra0 = tid >> 2;          // 0..63
    const int ra1 = ra0 + 64;          // 64..127
    const int ac  = tid & 3;           // 16B chunk within 64B row
    const __half *pA0, *pA1;
    if (G1) {
        int m0g = mt * 128 + ra0, m1g = mt * 128 + ra1;
        int t0 = (m0g < T) ? g_bucket[e][m0g] : 0;
        int t1 = (m1g < T) ? g_bucket[e][m1g] : 0;
        pA0 = g_x16 + (size_t)t0 * KTOT;
        pA1 = g_x16 + (size_t)t1 * KTOT;
    } else {
        const __half* aBase = g_h + ((size_t)e * NTOK + mt * 128) * KTOT;
        pA0 = aBase + (size_t)ra0 * KTOT;
        pA1 = aBase + (size_t)ra1 * KTOT;
    }
    const int apc0 = ac ^ ((ra0 >> 1) & 3);
    const int apc1 = ac ^ ((ra1 >> 1) & 3);

    float acc[4][8][4];
#pragma unroll
    for (int mi = 0; mi < 4; mi++)
#pragma unroll
        for (int ni = 0; ni < 8; ni++)
#pragma unroll
            for (int r = 0; r < 4; r++) acc[mi][ni][r] = 0.0f;

    // stage: A 128x32 (8KB) at +0, B 256x32 (16KB) at +8192
    auto load_chunk = [&](int kc, int stg) {
        const int kk = kc * 32;
        const uint32_t abase = sm + stg * STAGE_B;
        const uint32_t bbase = abase + 8192;
        cpa16(abase + ra0 * 64 + apc0 * 16, pA0 + kk + ac * 8);
        cpa16(abase + ra1 * 64 + apc1 * 16, pA1 + kk + ac * 8);
        const __half* bsrc = bBase + kk;
#pragma unroll
        for (int i = 0; i < 4; i++) {   // B: 1024 x 16B units
            int u = tid + i * 256;
            int row = u >> 2, c = u & 3;
            int pc = c ^ ((row >> 1) & 3);
            cpa16(bbase + row * 64 + pc * 16, bsrc + (size_t)row * KTOT + c * 8);
        }
    };

    // register fragments for k-half kh (0..1) of stage stg
    auto frag_load = [&](int stg, int kh, uint32_t a[4][4], uint32_t b[8][2]) {
        const uint32_t sA = sm + stg * STAGE_B;
        const uint32_t sB = sA + 8192;
#pragma unroll
        for (int mi = 0; mi < 4; mi++) {
            int row = warp_m * 64 + mi * 16 + (lane & 15);
            int c = kh * 2 + (lane >> 4);
            int pc = c ^ ((row >> 1) & 3);
            ldm_x4(a[mi], sA + row * 64 + pc * 16);
        }
#pragma unroll
        for (int p = 0; p < 4; p++) {   // each x4: 2 n-groups x 2 k-halves
            int row = warp_n * 64 + p * 16 + ((lane >> 4) & 1) * 8 + (lane & 7);
            int c = kh * 2 + ((lane >> 3) & 1);
            int pc = c ^ ((row >> 1) & 3);
            uint32_t t[4];
            ldm_x4(t, sB + row * 64 + pc * 16);
            b[p * 2][0] = t[0]; b[p * 2][1] = t[1];
            b[p * 2 + 1][0] = t[2]; b[p * 2 + 1][1] = t[3];
        }
    };

    uint32_t af[2][4][4], bf[2][8][2];

    // prologue: prefetch chunks 0..2
#pragma unroll
    for (int s = 0; s < GSTAGES - 1; s++) {
        if (s < NC) load_chunk(s, s);
        cpa_commit();
    }

    for (int kc = 0; kc < NC; kc++) {
        cpa_wait<GSTAGES - 2>();
        __syncthreads();
        const int nx = kc + GSTAGES - 1;
        if (nx < NC) load_chunk(nx, nx & (GSTAGES - 1));
        cpa_commit();
        const int stg = kc & (GSTAGES - 1);
        frag_load(stg, 0, af[0], bf[0]);
#pragma unroll
        for (int kh = 0; kh < 2; kh++) {
            if (kh == 0) frag_load(stg, 1, af[1], bf[1]);
            uint32_t (*a)[4] = af[kh];
            uint32_t (*b)[2] = bf[kh];
#pragma unroll
            for (int mi = 0; mi < 4; mi++)
#pragma unroll
                for (int ni = 0; ni < 8; ni++)
                    mma16816(acc[mi][ni], a[mi], b[ni]);
        }
    }

    // ----- epilogue -----
#pragma unroll
    for (int mi = 0; mi < 4; mi++) {
        const int m0 = mt * 128 + warp_m * 64 + mi * 16 + (lane >> 2);
#pragma unroll
        for (int half = 0; half < 2; half++) {
            const int m = m0 + half * 8;
            if (m >= T) continue;
            if (G1) {
                const size_t hrow = ((size_t)e * NTOK + m) * HDIM;
#pragma unroll
                for (int ni = 0; ni < 8; ni++) {
                    int n = jt * 256 + warp_n * 64 + ni * 8 + (lane & 3) * 2;
                    float v0 = acc[mi][ni][half * 2 + 0] + bias[e * NDIM + n];
                    float v1 = acc[mi][ni][half * 2 + 1] + bias[e * NDIM + n + 1];
                    float g0 = 0.5f * v0 * (1.0f + erff(v0 * 0.70710678118654752f));
                    float g1 = 0.5f * v1 * (1.0f + erff(v1 * 0.70710678118654752f));
                    *reinterpret_cast<__half2*>(g_h + hrow + n) =
                        __floats2half2_rn(g0, g1);
                }
            } else {
                const int tokn = g_bucket[e][m];
                const float wc = g_wt[e][m];
                const int sl = g_slot[e][m];
                float* prow = g_part[sl] + (size_t)tokn * CDIM;
#pragma unroll
                for (int ni = 0; ni < 8; ni++) {
                    int n = jt * 256 + warp_n * 64 + ni * 8 + (lane & 3) * 2;
                    float v0 = acc[mi][ni][half * 2 + 0] + bias[e * NDIM + n];
                    float v1 = acc[mi][ni][half * 2 + 1] + bias[e * NDIM + n + 1];
                    float2 st; st.x = wc * v0; st.y = wc * v1;
                    *reinterpret_cast<float2*>(prow + n) = st;
                }
            }
        }
    }
}

// ---------------------------------------------------------------------------
// Launch: fork converts onto side streams (concurrent with gate); join
// before their consumers. Streams/events are host objects created once.
// ---------------------------------------------------------------------------
extern "C" void kernel_launch(void* const* d_in, const int* in_sizes, int n_in,
                              void* d_out, int out_size) {
    const float* x  = (const float*)d_in[0];
    const float* gw = (const float*)d_in[1];
    const float* w1 = (const float*)d_in[2];
    const float* b1 = (const float*)d_in[3];
    const float* w2 = (const float*)d_in[4];
    const float* b2 = (const float*)d_in[5];
    float* out = (float*)d_out;

    static cudaStream_t s1 = nullptr, s2 = nullptr, s3 = nullptr;
    static cudaEvent_t e_fork = nullptr, e_w1 = nullptr, e_w2 = nullptr,
                       e_cx = nullptr;
    if (s1 == nullptr) {
        cudaStreamCreateWithFlags(&s1, cudaStreamNonBlocking);
        cudaStreamCreateWithFlags(&s2, cudaStreamNonBlocking);
        cudaStreamCreateWithFlags(&s3, cudaStreamNonBlocking);
        cudaEventCreateWithFlags(&e_fork, cudaEventDisableTiming);
        cudaEventCreateWithFlags(&e_w1, cudaEventDisableTiming);
        cudaEventCreateWithFlags(&e_w2, cudaEventDisableTiming);
        cudaEventCreateWithFlags(&e_cx, cudaEventDisableTiming);
        cudaFuncSetAttribute((const void*)moe_gemm_kernel<CDIM, HDIM, true>,
                             cudaFuncAttributeMaxDynamicSharedMemorySize, GSMEM);
        cudaFuncSetAttribute((const void*)moe_gemm_kernel<HDIM, CDIM, false>,
                             cudaFuncAttributeMaxDynamicSharedMemorySize, GSMEM);
    }

    // fork point on the (possibly capturing) default stream
    cudaEventRecord(e_fork, 0);
    cudaStreamWaitEvent(s1, e_fork, 0);
    cudaStreamWaitEvent(s2, e_fork, 0);
    cudaStreamWaitEvent(s3, e_fork, 0);

    // side streams: weight transposes + x convert (all independent of gate)
    convert_w_kernel<CDIM, HDIM, true>
        <<<dim3(HDIM / 32, CDIM / 32, NEXP), 256, 0, s1>>>(w1);
    cudaEventRecord(e_w1, s1);
    convert_w_kernel<HDIM, CDIM, false>
        <<<dim3(CDIM / 32, HDIM / 32, NEXP), 256, 0, s2>>>(w2);
    cudaEventRecord(e_w2, s2);
    convert_x_kernel<<<NTOK * CDIM / 4 / 256, 256, 0, s3>>>(x);
    cudaEventRecord(e_cx, s3);

    // main stream: routing
    init_kernel<<<1, 32>>>();
    gate_kernel<<<NTOK / 8, 256>>>(x, gw);

    // GEMM1 (needs w1t + routing + x16)
    cudaStreamWaitEvent(0, e_w1, 0);
    cudaStreamWaitEvent(0, e_cx, 0);
    moe_gemm_kernel<CDIM, HDIM, true>
        <<<dim3(HDIM / 256, NTOK / 128, NEXP), 256, GSMEM>>>(b1);

    // GEMM2 (needs w2t + g_h)
    cudaStreamWaitEvent(0, e_w2, 0);
    moe_gemm_kernel<HDIM, CDIM, false>
        <<<dim3(CDIM / 256, NTOK / 128, NEXP), 256, GSMEM>>>(b2);

    // combine slot partials into the output
    combine_kernel<<<NTOK * CDIM / 4 / 256, 256>>>(out);
}